// round 16
// baseline (speedup 1.0000x reference)
#include <cuda_runtime.h>
#include <cuda_bf16.h>
#include <cstdint>

#define N_NODES 50000
#define N_EDGES 800000
#define F 128
#define NCLS 47

#define SCAN_CHUNK 512
#define SCAN_BLOCKS ((N_NODES + SCAN_CHUNK - 1) / SCAN_CHUNK)  // 98

// ---------------- scratch (device globals; no allocation allowed) ----------------
__device__ int   g_deg[N_NODES];
__device__ int   g_row_ptr[N_NODES + 1];
__device__ int   g_cursor[N_NODES];
__device__ int   g_csr_src[N_EDGES];
__device__ int   g_bsum[SCAN_BLOCKS];
__device__ int   g_boff[SCAN_BLOCKS];
__device__ float g_hn[N_NODES * F];    // neighbor mean (layers 0/1)
__device__ float g_h1[N_NODES * F];    // layer-0 output
__device__ float g_h2[N_NODES * F];    // layer-1 output
__device__ float g_q2[N_NODES * 64];   // layer-2 neighbor projection (47 padded to 64)

// =============================== helpers ====================================
__device__ __forceinline__ float tf32r(float x) {
    float y;
    asm("cvt.rna.tf32.f32 %0, %1;" : "=f"(y) : "f"(x));
    return y;
}

__device__ __forceinline__ void mma_tf32(float* c, uint32_t a0, uint32_t a1,
                                         uint32_t a2, uint32_t a3,
                                         uint32_t b0, uint32_t b1) {
    asm volatile(
        "mma.sync.aligned.m16n8k8.row.col.f32.tf32.tf32.f32 "
        "{%0,%1,%2,%3}, {%4,%5,%6,%7}, {%8,%9}, {%0,%1,%2,%3};"
        : "+f"(c[0]), "+f"(c[1]), "+f"(c[2]), "+f"(c[3])
        : "r"(a0), "r"(a1), "r"(a2), "r"(a3), "r"(b0), "r"(b1));
}

// ---------------- CSR build ----------------
__global__ void zero_deg_kernel() {
    int i = blockIdx.x * blockDim.x + threadIdx.x;
    if (i < N_NODES) g_deg[i] = 0;
}

__global__ void hist_kernel(const int* __restrict__ dst) {
    int e = blockIdx.x * blockDim.x + threadIdx.x;
    if (e < N_EDGES) atomicAdd(&g_deg[dst[e]], 1);
}

// phase 1: per-block sums of 512-node chunks
__global__ void scan_phase1() {
    __shared__ int sh[256];
    int b = blockIdx.x, tid = threadIdx.x;
    int base = b * SCAN_CHUNK + tid * 2;
    int s = 0;
    if (base < N_NODES)     s += g_deg[base];
    if (base + 1 < N_NODES) s += g_deg[base + 1];
    sh[tid] = s;
    __syncthreads();
    for (int off = 128; off; off >>= 1) {
        if (tid < off) sh[tid] += sh[tid + off];
        __syncthreads();
    }
    if (tid == 0) g_bsum[b] = sh[0];
}

// phase 2: exclusive scan of the 98 block sums (single tiny block)
__global__ void scan_phase2() {
    __shared__ int sh[128];
    int tid = threadIdx.x;
    int v = (tid < SCAN_BLOCKS) ? g_bsum[tid] : 0;
    sh[tid] = v;
    __syncthreads();
    for (int off = 1; off < 128; off <<= 1) {
        int x = sh[tid];
        int a = (tid >= off) ? sh[tid - off] : 0;
        __syncthreads();
        sh[tid] = x + a;
        __syncthreads();
    }
    if (tid < SCAN_BLOCKS) g_boff[tid] = sh[tid] - v;
    if (tid == 0) g_row_ptr[N_NODES] = N_EDGES;
}

// phase 3: in-block exclusive scan + offset -> row_ptr / cursor
__global__ void scan_phase3() {
    __shared__ int sh[256];
    int b = blockIdx.x, tid = threadIdx.x;
    int base = b * SCAN_CHUNK + tid * 2;
    int v0 = (base < N_NODES)     ? g_deg[base]     : 0;
    int v1 = (base + 1 < N_NODES) ? g_deg[base + 1] : 0;
    int s = v0 + v1;
    sh[tid] = s;
    __syncthreads();
    for (int off = 1; off < 256; off <<= 1) {
        int x = sh[tid];
        int a = (tid >= off) ? sh[tid - off] : 0;
        __syncthreads();
        sh[tid] = x + a;
        __syncthreads();
    }
    int excl = sh[tid] - s + g_boff[b];
    if (base < N_NODES)     { g_row_ptr[base]     = excl;      g_cursor[base]     = excl; }
    if (base + 1 < N_NODES) { g_row_ptr[base + 1] = excl + v0; g_cursor[base + 1] = excl + v0; }
}

__global__ void csr_fill_kernel(const int* __restrict__ src, const int* __restrict__ dst) {
    int e = blockIdx.x * blockDim.x + threadIdx.x;
    if (e < N_EDGES) {
        int pos = atomicAdd(&g_cursor[dst[e]], 1);
        g_csr_src[pos] = src[e];
    }
}

// ------- 128-dim aggregation: TWO warps per node (half edge-range each) -----------
// Halves the per-node serial L2-gather chain; partials combined via smem.
// Block = 256 thr = 8 warps = 4 nodes.
__global__ void aggregate_kernel(const float* __restrict__ h) {
    __shared__ float4 part[8][32];
    const int wl   = threadIdx.x >> 5;   // warp in block: 0..7
    const int lane = threadIdx.x & 31;
    const int node = blockIdx.x * 4 + (wl >> 1);
    const int half = wl & 1;

    float4 acc = make_float4(0.f, 0.f, 0.f, 0.f);
    if (node < N_NODES) {
        const int s0 = g_row_ptr[node];
        const int s1 = g_row_ptr[node + 1];
        const int mid = s0 + ((s1 - s0) >> 1);
        int e  = half ? mid : s0;
        const int ee = half ? s1 : mid;
        const float4* hv = (const float4*)h;
        for (; e + 3 < ee; e += 4) {
            int i0 = g_csr_src[e];
            int i1 = g_csr_src[e + 1];
            int i2 = g_csr_src[e + 2];
            int i3 = g_csr_src[e + 3];
            float4 v0 = hv[i0 * 32 + lane];
            float4 v1 = hv[i1 * 32 + lane];
            float4 v2 = hv[i2 * 32 + lane];
            float4 v3 = hv[i3 * 32 + lane];
            acc.x += (v0.x + v1.x) + (v2.x + v3.x);
            acc.y += (v0.y + v1.y) + (v2.y + v3.y);
            acc.z += (v0.z + v1.z) + (v2.z + v3.z);
            acc.w += (v0.w + v1.w) + (v2.w + v3.w);
        }
        for (; e < ee; e++) {
            int i0 = g_csr_src[e];
            float4 v0 = hv[i0 * 32 + lane];
            acc.x += v0.x; acc.y += v0.y; acc.z += v0.z; acc.w += v0.w;
        }
    }
    part[wl][lane] = acc;
    __syncthreads();

    if (threadIdx.x < 128) {
        const int nl = threadIdx.x >> 5;      // local node 0..3
        const int ln = threadIdx.x & 31;
        const int n2 = blockIdx.x * 4 + nl;
        if (n2 < N_NODES) {
            float4 p0 = part[2 * nl][ln];
            float4 p1 = part[2 * nl + 1][ln];
            int s0 = g_row_ptr[n2], s1 = g_row_ptr[n2 + 1];
            float inv = (s1 > s0) ? 1.0f / (float)(s1 - s0) : 0.0f;
            float4 o;
            o.x = (p0.x + p1.x) * inv;
            o.y = (p0.y + p1.y) * inv;
            o.z = (p0.z + p1.z) * inv;
            o.w = (p0.w + p1.w) * inv;
            ((float4*)g_hn)[n2 * 32 + ln] = o;
        }
    }
}

// ------- 64-dim (padded-47) aggregation for layer 2: warp per node ----------------
// Lanes 0-15 gather the first half of the edge range, lanes 16-31 the second;
// partials combined with shfl_xor(.,16). Lane hl owns float4 #hl of the row.
__global__ void aggregate_out_kernel(const float* __restrict__ q, float* __restrict__ out) {
    int gw   = (blockIdx.x * blockDim.x + threadIdx.x) >> 5;
    int lane = threadIdx.x & 31;
    if (gw >= N_NODES) return;
    const int node = gw;
    const int hl   = lane & 15;
    const int half = lane >> 4;
    const int s0 = g_row_ptr[node];
    const int s1 = g_row_ptr[node + 1];
    const int mid = s0 + ((s1 - s0) >> 1);
    int e  = half ? mid : s0;
    const int ee = half ? s1 : mid;
    float4 acc = make_float4(0.f, 0.f, 0.f, 0.f);
    const float4* qv = (const float4*)q;
    for (; e + 3 < ee; e += 4) {
        int i0 = g_csr_src[e];
        int i1 = g_csr_src[e + 1];
        int i2 = g_csr_src[e + 2];
        int i3 = g_csr_src[e + 3];
        float4 v0 = qv[i0 * 16 + hl];
        float4 v1 = qv[i1 * 16 + hl];
        float4 v2 = qv[i2 * 16 + hl];
        float4 v3 = qv[i3 * 16 + hl];
        acc.x += (v0.x + v1.x) + (v2.x + v3.x);
        acc.y += (v0.y + v1.y) + (v2.y + v3.y);
        acc.z += (v0.z + v1.z) + (v2.z + v3.z);
        acc.w += (v0.w + v1.w) + (v2.w + v3.w);
    }
    for (; e < ee; e++) {
        int i0 = g_csr_src[e];
        float4 v0 = qv[i0 * 16 + hl];
        acc.x += v0.x; acc.y += v0.y; acc.z += v0.z; acc.w += v0.w;
    }
    // combine halves (lane <-> lane+16 hold the same float4 slot)
    acc.x += __shfl_xor_sync(0xffffffffu, acc.x, 16);
    acc.y += __shfl_xor_sync(0xffffffffu, acc.y, 16);
    acc.z += __shfl_xor_sync(0xffffffffu, acc.z, 16);
    acc.w += __shfl_xor_sync(0xffffffffu, acc.w, 16);
    if (half == 0) {
        float inv = (s1 > s0) ? 1.0f / (float)(s1 - s0) : 0.0f;
        float vals[4] = {acc.x * inv, acc.y * inv, acc.z * inv, acc.w * inv};
        int c0 = hl * 4;
#pragma unroll
        for (int i = 0; i < 4; i++) {
            int c = c0 + i;
            if (c < NCLS) out[(size_t)node * NCLS + c] += vals[i];
        }
    }
}

// ============== mma.sync tf32 fused GEMM:  [h | hn] @ [Wself;Wneigh] + epilogue ===
template <int NOUT, int NPAD, int NTN, bool DOLN>
__global__ void __launch_bounds__(256, 1) sage_gemm_mma(
    const float* __restrict__ Ah, const float* __restrict__ An,
    const float* __restrict__ Wself, const float* __restrict__ Wneigh,
    const float* __restrict__ bias, const float* __restrict__ gamma,
    const float* __restrict__ beta, float* __restrict__ out)
{
    extern __shared__ float smem[];
    float* Wsh    = smem;                       // 256 * NPAD
    float* Ash    = smem + 256 * NPAD;          // 128 * 128
    float* bias_s = Ash + 128 * 128;            // NPAD
    float* g_s    = bias_s + NPAD;              // NPAD
    float* be_s   = g_s + NPAD;                 // NPAD

    const int tid = threadIdx.x, wid = tid >> 5, lane = tid & 31;

    for (int i = tid; i < 256 * NPAD; i += 256) {
        int k = i / NPAD, n = i % NPAD;
        float w = 0.f;
        if (n < NOUT) w = (k < 128) ? Wself[k * NOUT + n] : Wneigh[(k - 128) * NOUT + n];
        Wsh[k * NPAD + (n ^ ((k & 3) << 3))] = tf32r(w);
    }
    for (int i = tid; i < NPAD; i += 256) {
        bias_s[i] = (i < NOUT) ? bias[i] : 0.f;
        if (DOLN) {
            g_s[i]  = (i < NOUT) ? gamma[i] : 0.f;
            be_s[i] = (i < NOUT) ? beta[i]  : 0.f;
        }
    }
    __syncthreads();

    const int NT = (N_NODES + 127) / 128;
    const int ra   = wid * 16 + (lane >> 2);
    const int aswz = (ra & 7) << 2;
    const int bswz = (lane & 3) << 3;
    const int nb   = lane >> 2;

    for (int t = blockIdx.x; t < NT; t += gridDim.x) {
        const int row0 = t * 128;

        float acc[NTN][4];
#pragma unroll
        for (int j = 0; j < NTN; j++)
#pragma unroll
            for (int q = 0; q < 4; q++) acc[j][q] = 0.f;

#pragma unroll
        for (int half = 0; half < 2; half++) {
            const float* srcp = half ? An : Ah;
            for (int i = tid; i < 128 * 32; i += 256) {
                int r = i >> 5, q = i & 31;
                int row = row0 + r;
                float4 v = make_float4(0.f, 0.f, 0.f, 0.f);
                if (row < N_NODES) {
                    v = ((const float4*)(srcp + (size_t)row * F))[q];
                    v.x = tf32r(v.x); v.y = tf32r(v.y);
                    v.z = tf32r(v.z); v.w = tf32r(v.w);
                }
                ((float4*)Ash)[r * 32 + (q ^ (r & 7))] = v;
            }
            __syncthreads();

#pragma unroll
            for (int step = 0; step < 16; step++) {
                const int k0 = step * 8;
                const int ka = k0 + (lane & 3);
                uint32_t a0 = __float_as_uint(Ash[ra * 128 + (ka ^ aswz)]);
                uint32_t a1 = __float_as_uint(Ash[(ra + 8) * 128 + (ka ^ aswz)]);
                uint32_t a2 = __float_as_uint(Ash[ra * 128 + ((ka + 4) ^ aswz)]);
                uint32_t a3 = __float_as_uint(Ash[(ra + 8) * 128 + ((ka + 4) ^ aswz)]);
                const int kb = half * 128 + k0 + (lane & 3);
                const float* wrow0 = Wsh + kb * NPAD;
                const float* wrow1 = wrow0 + 4 * NPAD;
#pragma unroll
                for (int j = 0; j < NTN; j++) {
                    int csw = (j * 8 + nb) ^ bswz;
                    uint32_t b0 = __float_as_uint(wrow0[csw]);
                    uint32_t b1 = __float_as_uint(wrow1[csw]);
                    mma_tf32(acc[j], a0, a1, a2, a3, b0, b1);
                }
            }
            __syncthreads();
        }

#pragma unroll
        for (int h = 0; h < 2; h++) {
            const int row = row0 + wid * 16 + (lane >> 2) + h * 8;
            float v[2 * NTN];
#pragma unroll
            for (int j = 0; j < NTN; j++) {
                int c0 = j * 8 + 2 * (lane & 3);
                v[2 * j]     = acc[j][2 * h]     + bias_s[c0];
                v[2 * j + 1] = acc[j][2 * h + 1] + bias_s[c0 + 1];
            }
            if (DOLN) {
                float s = 0.f;
#pragma unroll
                for (int q = 0; q < 2 * NTN; q++) s += v[q];
                s += __shfl_xor_sync(0xffffffffu, s, 1);
                s += __shfl_xor_sync(0xffffffffu, s, 2);
                float mean = s * (1.0f / (float)NOUT);
                float qv = 0.f;
#pragma unroll
                for (int q = 0; q < 2 * NTN; q++) { float d = v[q] - mean; qv += d * d; }
                qv += __shfl_xor_sync(0xffffffffu, qv, 1);
                qv += __shfl_xor_sync(0xffffffffu, qv, 2);
                float rs = rsqrtf(qv * (1.0f / (float)NOUT) + 1e-5f);
#pragma unroll
                for (int j = 0; j < NTN; j++) {
                    int c0 = j * 8 + 2 * (lane & 3);
                    v[2 * j]     = fmaxf((v[2 * j]     - mean) * rs * g_s[c0]     + be_s[c0],     0.f);
                    v[2 * j + 1] = fmaxf((v[2 * j + 1] - mean) * rs * g_s[c0 + 1] + be_s[c0 + 1], 0.f);
                }
            }
            if (row < N_NODES) {
#pragma unroll
                for (int j = 0; j < NTN; j++) {
                    int c0 = j * 8 + 2 * (lane & 3);
                    if (c0 + 1 < NOUT)
                        *(float2*)(out + (size_t)row * NOUT + c0) = make_float2(v[2 * j], v[2 * j + 1]);
                    else if (c0 < NOUT)
                        out[(size_t)row * NOUT + c0] = v[2 * j];
                }
            }
        }
        __syncthreads();
    }
}

// ======== layer-2 GEMM: h2 @ [Ws2 | Wn2] (K=128, 94 cols padded to 96) ===========
__global__ void __launch_bounds__(256, 1) sage_gemm_out(
    const float* __restrict__ Ah,
    const float* __restrict__ Wself, const float* __restrict__ Wneigh,
    const float* __restrict__ bias,
    float* __restrict__ out, float* __restrict__ q)
{
    constexpr int NPAD = 96, NTN = 12;
    extern __shared__ float smem[];
    float* Wsh    = smem;                 // 128 * 96
    float* Ash    = smem + 128 * NPAD;    // 128 * 128
    float* bias_s = Ash + 128 * 128;      // 96

    const int tid = threadIdx.x, wid = tid >> 5, lane = tid & 31;

    for (int i = tid; i < 128 * NPAD; i += 256) {
        int k = i / NPAD, n = i % NPAD;
        float w = 0.f;
        if (n < NCLS)           w = Wself[k * NCLS + n];
        else if (n < 2 * NCLS)  w = Wneigh[k * NCLS + (n - NCLS)];
        Wsh[k * NPAD + (n ^ ((k & 3) << 3))] = tf32r(w);
    }
    for (int i = tid; i < NPAD; i += 256)
        bias_s[i] = (i < NCLS) ? bias[i] : 0.f;
    __syncthreads();

    const int NT = (N_NODES + 127) / 128;
    const int ra   = wid * 16 + (lane >> 2);
    const int aswz = (ra & 7) << 2;
    const int bswz = (lane & 3) << 3;
    const int nb   = lane >> 2;

    for (int t = blockIdx.x; t < NT; t += gridDim.x) {
        const int row0 = t * 128;

        float acc[NTN][4];
#pragma unroll
        for (int j = 0; j < NTN; j++)
#pragma unroll
            for (int w4 = 0; w4 < 4; w4++) acc[j][w4] = 0.f;

        for (int i = tid; i < 128 * 32; i += 256) {
            int r = i >> 5, qq = i & 31;
            int row = row0 + r;
            float4 v = make_float4(0.f, 0.f, 0.f, 0.f);
            if (row < N_NODES) {
                v = ((const float4*)(Ah + (size_t)row * F))[qq];
                v.x = tf32r(v.x); v.y = tf32r(v.y);
                v.z = tf32r(v.z); v.w = tf32r(v.w);
            }
            ((float4*)Ash)[r * 32 + (qq ^ (r & 7))] = v;
        }
        __syncthreads();

#pragma unroll
        for (int step = 0; step < 16; step++) {
            const int k0 = step * 8;
            const int ka = k0 + (lane & 3);
            uint32_t a0 = __float_as_uint(Ash[ra * 128 + (ka ^ aswz)]);
            uint32_t a1 = __float_as_uint(Ash[(ra + 8) * 128 + (ka ^ aswz)]);
            uint32_t a2 = __float_as_uint(Ash[ra * 128 + ((ka + 4) ^ aswz)]);
            uint32_t a3 = __float_as_uint(Ash[(ra + 8) * 128 + ((ka + 4) ^ aswz)]);
            const int kb = k0 + (lane & 3);
            const float* wrow0 = Wsh + kb * NPAD;
            const float* wrow1 = wrow0 + 4 * NPAD;
#pragma unroll
            for (int j = 0; j < NTN; j++) {
                int csw = (j * 8 + nb) ^ bswz;
                uint32_t b0 = __float_as_uint(wrow0[csw]);
                uint32_t b1 = __float_as_uint(wrow1[csw]);
                mma_tf32(acc[j], a0, a1, a2, a3, b0, b1);
            }
        }
        __syncthreads();

#pragma unroll
        for (int h = 0; h < 2; h++) {
            const int row = row0 + wid * 16 + (lane >> 2) + h * 8;
            if (row < N_NODES) {
#pragma unroll
                for (int j = 0; j < NTN; j++) {
                    int c0 = j * 8 + 2 * (lane & 3);
#pragma unroll
                    for (int u = 0; u < 2; u++) {
                        int c = c0 + u;
                        float vv = acc[j][2 * h + u] + bias_s[c];
                        if (c < NCLS)
                            out[(size_t)row * NCLS + c] = vv;
                        else if (c < 2 * NCLS)
                            q[(size_t)row * 64 + (c - NCLS)] = vv;
                    }
                }
            }
        }
        __syncthreads();
    }
}

// ---------------- launch ----------------
extern "C" void kernel_launch(void* const* d_in, const int* in_sizes, int n_in,
                              void* d_out, int out_size) {
    const float* x   = (const float*)d_in[0];
    const int*   src = (const int*)d_in[1];
    const int*   dst = (const int*)d_in[2];
    const float* ws0 = (const float*)d_in[3];
    const float* wn0 = (const float*)d_in[4];
    const float* b0  = (const float*)d_in[5];
    const float* gm0 = (const float*)d_in[6];
    const float* bt0 = (const float*)d_in[7];
    const float* ws1 = (const float*)d_in[8];
    const float* wn1 = (const float*)d_in[9];
    const float* b1  = (const float*)d_in[10];
    const float* gm1 = (const float*)d_in[11];
    const float* bt1 = (const float*)d_in[12];
    const float* ws2 = (const float*)d_in[13];
    const float* wn2 = (const float*)d_in[14];
    const float* b2  = (const float*)d_in[15];
    float* out = (float*)d_out;

    float *hn, *h1, *h2, *q2;
    cudaGetSymbolAddress((void**)&hn, g_hn);
    cudaGetSymbolAddress((void**)&h1, g_h1);
    cudaGetSymbolAddress((void**)&h2, g_h2);
    cudaGetSymbolAddress((void**)&q2, g_q2);

    const int SMEM_L01 = (256 * 128 + 128 * 128 + 3 * 128) * 4;  // 198144
    const int SMEM_L2  = (128 * 96 + 128 * 128 + 96) * 4;        // 115072
    cudaFuncSetAttribute(sage_gemm_mma<128, 128, 16, true>,
                         cudaFuncAttributeMaxDynamicSharedMemorySize, SMEM_L01);
    cudaFuncSetAttribute(sage_gemm_out,
                         cudaFuncAttributeMaxDynamicSharedMemorySize, SMEM_L2);

    // CSR build (reused by all 3 layers); parallel 3-phase scan
    zero_deg_kernel<<<(N_NODES + 255) / 256, 256>>>();
    hist_kernel<<<(N_EDGES + 255) / 256, 256>>>(dst);
    scan_phase1<<<SCAN_BLOCKS, 256>>>();
    scan_phase2<<<1, 128>>>();
    scan_phase3<<<SCAN_BLOCKS, 256>>>();
    csr_fill_kernel<<<(N_EDGES + 255) / 256, 256>>>(src, dst);

    const int AGG_BLOCKS  = (N_NODES + 3) / 4;                      // 2 warps per node
    const int AGG2_BLOCKS = (N_NODES * 32 + 255) / 256;             // warp per node

    // layer 0
    aggregate_kernel<<<AGG_BLOCKS, 256>>>(x);
    sage_gemm_mma<128, 128, 16, true><<<148, 256, SMEM_L01>>>(x, hn, ws0, wn0, b0, gm0, bt0, h1);
    // layer 1
    aggregate_kernel<<<AGG_BLOCKS, 256>>>(h1);
    sage_gemm_mma<128, 128, 16, true><<<148, 256, SMEM_L01>>>(h1, hn, ws1, wn1, b1, gm1, bt1, h2);
    // layer 2: project first (self->out, neigh->q2), then 47-dim aggregate adds into out
    sage_gemm_out<<<148, 256, SMEM_L2>>>(h2, ws2, wn2, b2, out, q2);
    aggregate_out_kernel<<<AGG2_BLOCKS, 256>>>(q2, out);
}

// round 17
// speedup vs baseline: 1.0968x; 1.0968x over previous
#include <cuda_runtime.h>
#include <cuda_bf16.h>
#include <cstdint>

#define N_NODES 50000
#define N_EDGES 800000
#define F 128
#define NCLS 47

#define SCAN_CHUNK 512
#define SCAN_BLOCKS ((N_NODES + SCAN_CHUNK - 1) / SCAN_CHUNK)  // 98

// B tile row stride in floats: 132 ≡ 4 (mod 32) words -> conflict-free LDS.128
#define WROW 132

// ---------------- scratch (device globals; no allocation allowed) ----------------
__device__ int   g_deg[N_NODES];
__device__ int   g_row_ptr[N_NODES + 1];
__device__ int   g_cursor[N_NODES];
__device__ int   g_csr_src[N_EDGES];
__device__ int   g_bsum[SCAN_BLOCKS];
__device__ int   g_boff[SCAN_BLOCKS];
__device__ float g_hn[N_NODES * F];    // neighbor mean (layers 0/1)
__device__ float g_h1[N_NODES * F];    // layer-0 output
__device__ float g_h2[N_NODES * F];    // layer-1 output
__device__ float g_q2[N_NODES * 64];   // layer-2 neighbor projection (47 padded to 64)

// =============================== helpers ====================================
__device__ __forceinline__ float tf32r(float x) {
    float y;
    asm("cvt.rna.tf32.f32 %0, %1;" : "=f"(y) : "f"(x));
    return y;
}

__device__ __forceinline__ void mma_tf32(float* c, uint32_t a0, uint32_t a1,
                                         uint32_t a2, uint32_t a3,
                                         uint32_t b0, uint32_t b1) {
    asm volatile(
        "mma.sync.aligned.m16n8k8.row.col.f32.tf32.tf32.f32 "
        "{%0,%1,%2,%3}, {%4,%5,%6,%7}, {%8,%9}, {%0,%1,%2,%3};"
        : "+f"(c[0]), "+f"(c[1]), "+f"(c[2]), "+f"(c[3])
        : "r"(a0), "r"(a1), "r"(a2), "r"(a3), "r"(b0), "r"(b1));
}

// ---------------- CSR build ----------------
__global__ void zero_deg_kernel() {
    int i = blockIdx.x * blockDim.x + threadIdx.x;
    if (i < N_NODES) g_deg[i] = 0;
}

__global__ void hist_kernel(const int* __restrict__ dst) {
    int e = blockIdx.x * blockDim.x + threadIdx.x;
    if (e < N_EDGES) atomicAdd(&g_deg[dst[e]], 1);
}

// phase 1: per-block sums of 512-node chunks
__global__ void scan_phase1() {
    __shared__ int sh[256];
    int b = blockIdx.x, tid = threadIdx.x;
    int base = b * SCAN_CHUNK + tid * 2;
    int s = 0;
    if (base < N_NODES)     s += g_deg[base];
    if (base + 1 < N_NODES) s += g_deg[base + 1];
    sh[tid] = s;
    __syncthreads();
    for (int off = 128; off; off >>= 1) {
        if (tid < off) sh[tid] += sh[tid + off];
        __syncthreads();
    }
    if (tid == 0) g_bsum[b] = sh[0];
}

// phase 2: exclusive scan of the 98 block sums (single tiny block)
__global__ void scan_phase2() {
    __shared__ int sh[128];
    int tid = threadIdx.x;
    int v = (tid < SCAN_BLOCKS) ? g_bsum[tid] : 0;
    sh[tid] = v;
    __syncthreads();
    for (int off = 1; off < 128; off <<= 1) {
        int x = sh[tid];
        int a = (tid >= off) ? sh[tid - off] : 0;
        __syncthreads();
        sh[tid] = x + a;
        __syncthreads();
    }
    if (tid < SCAN_BLOCKS) g_boff[tid] = sh[tid] - v;
    if (tid == 0) g_row_ptr[N_NODES] = N_EDGES;
}

// phase 3: in-block exclusive scan + offset -> row_ptr / cursor
__global__ void scan_phase3() {
    __shared__ int sh[256];
    int b = blockIdx.x, tid = threadIdx.x;
    int base = b * SCAN_CHUNK + tid * 2;
    int v0 = (base < N_NODES)     ? g_deg[base]     : 0;
    int v1 = (base + 1 < N_NODES) ? g_deg[base + 1] : 0;
    int s = v0 + v1;
    sh[tid] = s;
    __syncthreads();
    for (int off = 1; off < 256; off <<= 1) {
        int x = sh[tid];
        int a = (tid >= off) ? sh[tid - off] : 0;
        __syncthreads();
        sh[tid] = x + a;
        __syncthreads();
    }
    int excl = sh[tid] - s + g_boff[b];
    if (base < N_NODES)     { g_row_ptr[base]     = excl;      g_cursor[base]     = excl; }
    if (base + 1 < N_NODES) { g_row_ptr[base + 1] = excl + v0; g_cursor[base + 1] = excl + v0; }
}

__global__ void csr_fill_kernel(const int* __restrict__ src, const int* __restrict__ dst) {
    int e = blockIdx.x * blockDim.x + threadIdx.x;
    if (e < N_EDGES) {
        int pos = atomicAdd(&g_cursor[dst[e]], 1);
        g_csr_src[pos] = src[e];
    }
}

// ------- 128-dim aggregation: warp per node, lane owns one float4, unroll-4 -------
// (round-13 form: empirically optimal; fp16/shfl/2-warp variants all regressed)
__global__ void aggregate_kernel(const float* __restrict__ h) {
    int gw   = (blockIdx.x * blockDim.x + threadIdx.x) >> 5;
    int lane = threadIdx.x & 31;
    if (gw >= N_NODES) return;
    const int node = gw;
    int s0 = g_row_ptr[node];
    int s1 = g_row_ptr[node + 1];
    float4 acc = make_float4(0.f, 0.f, 0.f, 0.f);
    const float4* hv = (const float4*)h;
    int e = s0;
    for (; e + 3 < s1; e += 4) {
        int i0 = g_csr_src[e];
        int i1 = g_csr_src[e + 1];
        int i2 = g_csr_src[e + 2];
        int i3 = g_csr_src[e + 3];
        float4 v0 = hv[i0 * 32 + lane];
        float4 v1 = hv[i1 * 32 + lane];
        float4 v2 = hv[i2 * 32 + lane];
        float4 v3 = hv[i3 * 32 + lane];
        acc.x += (v0.x + v1.x) + (v2.x + v3.x);
        acc.y += (v0.y + v1.y) + (v2.y + v3.y);
        acc.z += (v0.z + v1.z) + (v2.z + v3.z);
        acc.w += (v0.w + v1.w) + (v2.w + v3.w);
    }
    for (; e < s1; e++) {
        int i0 = g_csr_src[e];
        float4 v0 = hv[i0 * 32 + lane];
        acc.x += v0.x; acc.y += v0.y; acc.z += v0.z; acc.w += v0.w;
    }
    float inv = (s1 > s0) ? 1.0f / (float)(s1 - s0) : 0.0f;
    acc.x *= inv; acc.y *= inv; acc.z *= inv; acc.w *= inv;
    ((float4*)g_hn)[node * 32 + lane] = acc;
}

// ------- 64-dim (padded-47) aggregation for layer 2: half-warp per node ----------
__global__ void aggregate_out_kernel(const float* __restrict__ q, float* __restrict__ out) {
    int gw   = (blockIdx.x * blockDim.x + threadIdx.x) >> 5;
    int lane = threadIdx.x & 31;
    int half = lane >> 4;
    int hl   = lane & 15;
    int node = gw * 2 + half;
    if (node >= N_NODES) return;
    int s0 = g_row_ptr[node];
    int s1 = g_row_ptr[node + 1];
    float4 acc = make_float4(0.f, 0.f, 0.f, 0.f);
    const float4* qv = (const float4*)q;
    int e = s0;
    for (; e + 3 < s1; e += 4) {
        int i0 = g_csr_src[e];
        int i1 = g_csr_src[e + 1];
        int i2 = g_csr_src[e + 2];
        int i3 = g_csr_src[e + 3];
        float4 v0 = qv[i0 * 16 + hl];
        float4 v1 = qv[i1 * 16 + hl];
        float4 v2 = qv[i2 * 16 + hl];
        float4 v3 = qv[i3 * 16 + hl];
        acc.x += (v0.x + v1.x) + (v2.x + v3.x);
        acc.y += (v0.y + v1.y) + (v2.y + v3.y);
        acc.z += (v0.z + v1.z) + (v2.z + v3.z);
        acc.w += (v0.w + v1.w) + (v2.w + v3.w);
    }
    for (; e < s1; e++) {
        int i0 = g_csr_src[e];
        float4 v0 = qv[i0 * 16 + hl];
        acc.x += v0.x; acc.y += v0.y; acc.z += v0.z; acc.w += v0.w;
    }
    float inv = (s1 > s0) ? 1.0f / (float)(s1 - s0) : 0.0f;
    float vals[4] = {acc.x * inv, acc.y * inv, acc.z * inv, acc.w * inv};
    int c0 = hl * 4;
#pragma unroll
    for (int i = 0; i < 4; i++) {
        int c = c0 + i;
        if (c < NCLS) out[(size_t)node * NCLS + c] += vals[i];
    }
}

// ============== mma.sync tf32 fused GEMM:  [h | hn] @ [Wself;Wneigh] + epilogue ===
// B tile layout: Wsh[k*WROW + nb*16 + j] = W[k][j*8+nb]  (nb = lane>>2 group)
// -> per-thread B fragment for all 16 j is CONTIGUOUS: 4 x LDS.128 per k-row.
// WROW=132 (=4 mod 32 words): quarter-warp 4-word blocks kb*1 + nb*4 mod 8 distinct.
__global__ void __launch_bounds__(256, 1) sage_gemm_l01(
    const float* __restrict__ Ah, const float* __restrict__ An,
    const float* __restrict__ Wself, const float* __restrict__ Wneigh,
    const float* __restrict__ bias, const float* __restrict__ gamma,
    const float* __restrict__ beta, float* __restrict__ out)
{
    constexpr int NTN = 16, NOUT = 128;
    extern __shared__ float smem[];
    float* Wsh    = smem;                       // 256 * WROW
    float* Ash    = smem + 256 * WROW;          // 128 * 128
    float* bias_s = Ash + 128 * 128;            // 128
    float* g_s    = bias_s + 128;               // 128
    float* be_s   = g_s + 128;                  // 128

    const int tid = threadIdx.x, wid = tid >> 5, lane = tid & 31;

    // stage W: Wsh[k*WROW + (n&7)*16 + (n>>3)] = W[k][n]
    for (int i = tid; i < 256 * 128; i += 256) {
        int k = i >> 7, n = i & 127;
        float w = (k < 128) ? Wself[k * NOUT + n] : Wneigh[(k - 128) * NOUT + n];
        Wsh[k * WROW + (n & 7) * 16 + (n >> 3)] = tf32r(w);
    }
    for (int i = tid; i < 128; i += 256) {
        bias_s[i] = bias[i];
        g_s[i]    = gamma[i];
        be_s[i]   = beta[i];
    }
    __syncthreads();

    const int NT = (N_NODES + 127) / 128;
    const int ra   = wid * 16 + (lane >> 2);
    const int aswz = (ra & 7) << 2;
    const int nb   = lane >> 2;

    for (int t = blockIdx.x; t < NT; t += gridDim.x) {
        const int row0 = t * 128;

        float acc[NTN][4];
#pragma unroll
        for (int j = 0; j < NTN; j++)
#pragma unroll
            for (int q = 0; q < 4; q++) acc[j][q] = 0.f;

#pragma unroll
        for (int half = 0; half < 2; half++) {
            const float* srcp = half ? An : Ah;
            for (int i = tid; i < 128 * 32; i += 256) {
                int r = i >> 5, q = i & 31;
                int row = row0 + r;
                float4 v = make_float4(0.f, 0.f, 0.f, 0.f);
                if (row < N_NODES) {
                    v = ((const float4*)(srcp + (size_t)row * F))[q];
                    v.x = tf32r(v.x); v.y = tf32r(v.y);
                    v.z = tf32r(v.z); v.w = tf32r(v.w);
                }
                ((float4*)Ash)[r * 32 + (q ^ (r & 7))] = v;
            }
            __syncthreads();

#pragma unroll
            for (int step = 0; step < 16; step++) {
                const int k0 = step * 8;
                const int ka = k0 + (lane & 3);
                uint32_t a0 = __float_as_uint(Ash[ra * 128 + (ka ^ aswz)]);
                uint32_t a1 = __float_as_uint(Ash[(ra + 8) * 128 + (ka ^ aswz)]);
                uint32_t a2 = __float_as_uint(Ash[ra * 128 + ((ka + 4) ^ aswz)]);
                uint32_t a3 = __float_as_uint(Ash[(ra + 8) * 128 + ((ka + 4) ^ aswz)]);
                const int kb = half * 128 + k0 + (lane & 3);
                const float4* w0 = (const float4*)(Wsh + kb * WROW + nb * 16);
                const float4* w1 = (const float4*)(Wsh + (kb + 4) * WROW + nb * 16);
                float4 B0[4], B1[4];
                B0[0] = w0[0]; B0[1] = w0[1]; B0[2] = w0[2]; B0[3] = w0[3];
                B1[0] = w1[0]; B1[1] = w1[1]; B1[2] = w1[2]; B1[3] = w1[3];
                const float* bw0 = (const float*)B0;
                const float* bw1 = (const float*)B1;
#pragma unroll
                for (int j = 0; j < NTN; j++) {
                    mma_tf32(acc[j], a0, a1, a2, a3,
                             __float_as_uint(bw0[j]), __float_as_uint(bw1[j]));
                }
            }
            __syncthreads();
        }

#pragma unroll
        for (int h = 0; h < 2; h++) {
            const int row = row0 + wid * 16 + (lane >> 2) + h * 8;
            float v[2 * NTN];
#pragma unroll
            for (int j = 0; j < NTN; j++) {
                int c0 = j * 8 + 2 * (lane & 3);
                v[2 * j]     = acc[j][2 * h]     + bias_s[c0];
                v[2 * j + 1] = acc[j][2 * h + 1] + bias_s[c0 + 1];
            }
            float s = 0.f;
#pragma unroll
            for (int q = 0; q < 2 * NTN; q++) s += v[q];
            s += __shfl_xor_sync(0xffffffffu, s, 1);
            s += __shfl_xor_sync(0xffffffffu, s, 2);
            float mean = s * (1.0f / (float)NOUT);
            float qv = 0.f;
#pragma unroll
            for (int q = 0; q < 2 * NTN; q++) { float d = v[q] - mean; qv += d * d; }
            qv += __shfl_xor_sync(0xffffffffu, qv, 1);
            qv += __shfl_xor_sync(0xffffffffu, qv, 2);
            float rs = rsqrtf(qv * (1.0f / (float)NOUT) + 1e-5f);
#pragma unroll
            for (int j = 0; j < NTN; j++) {
                int c0 = j * 8 + 2 * (lane & 3);
                v[2 * j]     = fmaxf((v[2 * j]     - mean) * rs * g_s[c0]     + be_s[c0],     0.f);
                v[2 * j + 1] = fmaxf((v[2 * j + 1] - mean) * rs * g_s[c0 + 1] + be_s[c0 + 1], 0.f);
            }
            if (row < N_NODES) {
#pragma unroll
                for (int j = 0; j < NTN; j++) {
                    int c0 = j * 8 + 2 * (lane & 3);
                    *(float2*)(out + (size_t)row * NOUT + c0) = make_float2(v[2 * j], v[2 * j + 1]);
                }
            }
        }
        __syncthreads();
    }
}

// ======== layer-2 GEMM: h2 @ [Ws2 | Wn2] (K=128, 94 cols, j=0..11) ===============
__global__ void __launch_bounds__(256, 1) sage_gemm_out(
    const float* __restrict__ Ah,
    const float* __restrict__ Wself, const float* __restrict__ Wneigh,
    const float* __restrict__ bias,
    float* __restrict__ out, float* __restrict__ q)
{
    constexpr int NTN = 12;
    extern __shared__ float smem[];
    float* Wsh    = smem;                    // 128 * WROW
    float* Ash    = smem + 128 * WROW;       // 128 * 128
    float* bias_s = Ash + 128 * 128;         // 96

    const int tid = threadIdx.x, wid = tid >> 5, lane = tid & 31;

    for (int i = tid; i < 128 * 96; i += 256) {
        int k = i / 96, n = i % 96;
        float w = 0.f;
        if (n < NCLS)           w = Wself[k * NCLS + n];
        else if (n < 2 * NCLS)  w = Wneigh[k * NCLS + (n - NCLS)];
        Wsh[k * WROW + (n & 7) * 16 + (n >> 3)] = tf32r(w);
    }
    for (int i = tid; i < 96; i += 256)
        bias_s[i] = (i < NCLS) ? bias[i] : 0.f;
    __syncthreads();

    const int NT = (N_NODES + 127) / 128;
    const int ra   = wid * 16 + (lane >> 2);
    const int aswz = (ra & 7) << 2;
    const int nb   = lane >> 2;

    for (int t = blockIdx.x; t < NT; t += gridDim.x) {
        const int row0 = t * 128;

        float acc[NTN][4];
#pragma unroll
        for (int j = 0; j < NTN; j++)
#pragma unroll
            for (int w4 = 0; w4 < 4; w4++) acc[j][w4] = 0.f;

        for (int i = tid; i < 128 * 32; i += 256) {
            int r = i >> 5, qq = i & 31;
            int row = row0 + r;
            float4 v = make_float4(0.f, 0.f, 0.f, 0.f);
            if (row < N_NODES) {
                v = ((const float4*)(Ah + (size_t)row * F))[qq];
                v.x = tf32r(v.x); v.y = tf32r(v.y);
                v.z = tf32r(v.z); v.w = tf32r(v.w);
            }
            ((float4*)Ash)[r * 32 + (qq ^ (r & 7))] = v;
        }
        __syncthreads();

#pragma unroll
        for (int step = 0; step < 16; step++) {
            const int k0 = step * 8;
            const int ka = k0 + (lane & 3);
            uint32_t a0 = __float_as_uint(Ash[ra * 128 + (ka ^ aswz)]);
            uint32_t a1 = __float_as_uint(Ash[(ra + 8) * 128 + (ka ^ aswz)]);
            uint32_t a2 = __float_as_uint(Ash[ra * 128 + ((ka + 4) ^ aswz)]);
            uint32_t a3 = __float_as_uint(Ash[(ra + 8) * 128 + ((ka + 4) ^ aswz)]);
            const int kb = k0 + (lane & 3);
            const float4* w0 = (const float4*)(Wsh + kb * WROW + nb * 16);
            const float4* w1 = (const float4*)(Wsh + (kb + 4) * WROW + nb * 16);
            float4 B0[3], B1[3];
            B0[0] = w0[0]; B0[1] = w0[1]; B0[2] = w0[2];
            B1[0] = w1[0]; B1[1] = w1[1]; B1[2] = w1[2];
            const float* bw0 = (const float*)B0;
            const float* bw1 = (const float*)B1;
#pragma unroll
            for (int j = 0; j < NTN; j++) {
                mma_tf32(acc[j], a0, a1, a2, a3,
                         __float_as_uint(bw0[j]), __float_as_uint(bw1[j]));
            }
        }
        __syncthreads();

#pragma unroll
        for (int h = 0; h < 2; h++) {
            const int row = row0 + wid * 16 + (lane >> 2) + h * 8;
            if (row < N_NODES) {
#pragma unroll
                for (int j = 0; j < NTN; j++) {
                    int c0 = j * 8 + 2 * (lane & 3);
#pragma unroll
                    for (int u = 0; u < 2; u++) {
                        int c = c0 + u;
                        float vv = acc[j][2 * h + u] + bias_s[c];
                        if (c < NCLS)
                            out[(size_t)row * NCLS + c] = vv;
                        else if (c < 2 * NCLS)
                            q[(size_t)row * 64 + (c - NCLS)] = vv;
                    }
                }
            }
        }
        __syncthreads();
    }
}

// ---------------- launch ----------------
extern "C" void kernel_launch(void* const* d_in, const int* in_sizes, int n_in,
                              void* d_out, int out_size) {
    const float* x   = (const float*)d_in[0];
    const int*   src = (const int*)d_in[1];
    const int*   dst = (const int*)d_in[2];
    const float* ws0 = (const float*)d_in[3];
    const float* wn0 = (const float*)d_in[4];
    const float* b0  = (const float*)d_in[5];
    const float* gm0 = (const float*)d_in[6];
    const float* bt0 = (const float*)d_in[7];
    const float* ws1 = (const float*)d_in[8];
    const float* wn1 = (const float*)d_in[9];
    const float* b1  = (const float*)d_in[10];
    const float* gm1 = (const float*)d_in[11];
    const float* bt1 = (const float*)d_in[12];
    const float* ws2 = (const float*)d_in[13];
    const float* wn2 = (const float*)d_in[14];
    const float* b2  = (const float*)d_in[15];
    float* out = (float*)d_out;

    float *hn, *h1, *h2, *q2;
    cudaGetSymbolAddress((void**)&hn, g_hn);
    cudaGetSymbolAddress((void**)&h1, g_h1);
    cudaGetSymbolAddress((void**)&h2, g_h2);
    cudaGetSymbolAddress((void**)&q2, g_q2);

    const int SMEM_L01 = (256 * WROW + 128 * 128 + 3 * 128) * 4;  // 202240
    const int SMEM_L2  = (128 * WROW + 128 * 128 + 96) * 4;       // 133504
    cudaFuncSetAttribute(sage_gemm_l01,
                         cudaFuncAttributeMaxDynamicSharedMemorySize, SMEM_L01);
    cudaFuncSetAttribute(sage_gemm_out,
                         cudaFuncAttributeMaxDynamicSharedMemorySize, SMEM_L2);

    // CSR build (reused by all 3 layers); parallel 3-phase scan
    zero_deg_kernel<<<(N_NODES + 255) / 256, 256>>>();
    hist_kernel<<<(N_EDGES + 255) / 256, 256>>>(dst);
    scan_phase1<<<SCAN_BLOCKS, 256>>>();
    scan_phase2<<<1, 128>>>();
    scan_phase3<<<SCAN_BLOCKS, 256>>>();
    csr_fill_kernel<<<(N_EDGES + 255) / 256, 256>>>(src, dst);

    const int AGG_BLOCKS  = (N_NODES * 32 + 255) / 256;              // warp per node
    const int AGG2_BLOCKS = (((N_NODES + 1) / 2) * 32 + 255) / 256;  // half-warp per node

    // layer 0
    aggregate_kernel<<<AGG_BLOCKS, 256>>>(x);
    sage_gemm_l01<<<148, 256, SMEM_L01>>>(x, hn, ws0, wn0, b0, gm0, bt0, h1);
    // layer 1
    aggregate_kernel<<<AGG_BLOCKS, 256>>>(h1);
    sage_gemm_l01<<<148, 256, SMEM_L01>>>(h1, hn, ws1, wn1, b1, gm1, bt1, h2);
    // layer 2: project first (self->out, neigh->q2), then 47-dim aggregate adds into out
    sage_gemm_out<<<148, 256, SMEM_L2>>>(h2, ws2, wn2, b2, out, q2);
    aggregate_out_kernel<<<AGG2_BLOCKS, 256>>>(q2, out);
}